// round 13
// baseline (speedup 1.0000x reference)
#include <cuda_runtime.h>
#include <cuda_bf16.h>
#include <cstddef>
#include <cstdint>

#define NN 10000
#define NE 320000
#define DD 256

// ---------------- scratch (device globals; no runtime allocation) ----------
__device__ float g_H[2 * NN * DD];      // edge-NN layer-2 output (fp32, scatter src)
__device__ float g_agg[NN * DD];        // scatter-sum result
__device__ float g_gates[NN * 4 * DD];  // LSTM gates (f columns unwritten)
__device__ float g_bcomb[4 * DD];       // b_ih + b_hh

// bf16x3 split planes (plane stride = tensor element count)
__device__ uint16_t g_featP[3 * NN * DD];
__device__ uint16_t g_TP[3 * 2 * NN * DD];
__device__ uint16_t g_aggP[3 * NN * DD];
__device__ uint16_t g_hnP[3 * NN * DD];
__device__ uint16_t g_x1P[3 * NN * 128];
__device__ uint16_t g_x2P[3 * NN * 128];
__device__ uint16_t g_WrelP[3 * 2 * DD * DD];
__device__ uint16_t g_WihP[3 * 4 * DD * DD];
__device__ uint16_t g_W1P[3 * 128 * DD];
__device__ uint16_t g_W2P[3 * 128 * 128];
__device__ uint16_t g_W3P[3 * DD * 128];

// ---------------- portable helpers (NO a-suffix features) ------------------
__device__ __forceinline__ uint32_t smem_u32(const void* p)
{
    uint32_t a;
    asm("{ .reg .u64 t; cvta.to.shared.u64 t, %1; cvt.u32.u64 %0, t; }"
        : "=r"(a) : "l"(p));
    return a;
}

__device__ __forceinline__ void ldsm4(uint32_t* r, uint32_t addr)
{
    asm volatile("ldmatrix.sync.aligned.m8n8.x4.shared.b16 {%0,%1,%2,%3}, [%4];"
                 : "=r"(r[0]), "=r"(r[1]), "=r"(r[2]), "=r"(r[3]) : "r"(addr));
}

__device__ __forceinline__ void mma16(float* c, const uint32_t* a, const uint32_t* b)
{
    asm volatile(
        "mma.sync.aligned.m16n8k16.row.col.f32.bf16.bf16.f32 "
        "{%0,%1,%2,%3}, {%4,%5,%6,%7}, {%8,%9}, {%0,%1,%2,%3};"
        : "+f"(c[0]), "+f"(c[1]), "+f"(c[2]), "+f"(c[3])
        : "r"(a[0]), "r"(a[1]), "r"(a[2]), "r"(a[3]), "r"(b[0]), "r"(b[1]));
}

__device__ __forceinline__ void cpa16(uint32_t dst, const void* src, bool ok)
{
    int sz = ok ? 16 : 0;   // src-size 0 => zero-fill, no gmem access
    asm volatile("cp.async.cg.shared.global [%0], [%1], 16, %2;"
                 :: "r"(dst), "l"(src), "r"(sz) : "memory");
}
#define CP_COMMIT() asm volatile("cp.async.commit_group;" ::: "memory")

// exact 3-term bf16 split of a float pair, packed bf16x2 per level
__device__ __forceinline__ void split2pack(float a, float b,
                                           uint32_t& h, uint32_t& m, uint32_t& l)
{
    uint32_t ua = __float_as_uint(a), ub = __float_as_uint(b);
    h = __byte_perm(ua, ub, 0x7632);
    float ra = a - __uint_as_float(ua & 0xFFFF0000u);
    float rb = b - __uint_as_float(ub & 0xFFFF0000u);
    uint32_t wa = __float_as_uint(ra), wb = __float_as_uint(rb);
    m = __byte_perm(wa, wb, 0x7632);
    float sa = ra - __uint_as_float(wa & 0xFFFF0000u);
    float sb = rb - __uint_as_float(wb & 0xFFFF0000u);
    l = __byte_perm(__float_as_uint(sa), __float_as_uint(sb), 0x7632);
}

// ---------------- smem geometry ---------------------------------------------
// bf16 tile: 128 rows x 32 cols = 64 B/row = 8 KB. Per stage: A0 A1 A2 W0 W1 W2.
// Row layout: 4 chunks of 16B; swizzle chunk' = chunk ^ ((row>>1)&3) ->
// conflict-free for the 16B cp.async writes and 8-row ldmatrix fetches.
#define TILE_B  8192
#define STAGE_B (6 * TILE_B)
#define GSMEM   (3 * STAGE_B)           // 3-stage pipeline = 147456 B

// --------- bf16x6 tensor-core GEMM on pre-split planes ----------------------
// C = act(A @ W^T + bias). A planes: [M,K] rm bf16 x3; W planes: [N,K] rm x3.
// 128x128 block, BK=32, 512 threads = 16 warps (4m x 4n), warp 32x32.
// 6 products (sa+sb<=2) accumulate in fp32 -> ~fp32 accuracy.
// cp.async 3-stage pipeline; blockIdx.z batches via z* strides.
// SKIPF: remap column tiles >=2 -> +256 (skip dead LSTM f-gate columns).
// EMITF: write fp32 C. EMITP: write bf16x3 planes Cp (producer-side split).
template <int ACT, int SKIPF, int EMITF, int EMITP>
__global__ void __launch_bounds__(512)
tcgemm(const uint16_t* __restrict__ Ap, long Aplane, long zA,
       const uint16_t* __restrict__ Wp, long Wplane, long zW,
       const float* __restrict__ bias, long zB,
       float* __restrict__ C, long zC,
       uint16_t* __restrict__ Cp, long Cplane, long zCp,
       int M, int N, int K)
{
    Ap   += (long)blockIdx.z * zA;
    Wp   += (long)blockIdx.z * zW;
    bias += (long)blockIdx.z * zB;
    if (EMITF) C  += (long)blockIdx.z * zC;
    if (EMITP) Cp += (long)blockIdx.z * zCp;

    extern __shared__ char smc[];
    const uint32_t smb = smem_u32(smc);

    const int tid  = threadIdx.x;
    const int lane = tid & 31;
    const int wid  = tid >> 5;
    const int wm   = (wid & 3) * 32;
    const int wn   = (wid >> 2) * 32;

    const int m0 = blockIdx.y * 128;
    int n0 = blockIdx.x * 128;
    if (SKIPF && blockIdx.x >= 2) n0 += 256;

    // ---- copy mapping: thread -> (row 0..127, 8-col group) ----
    const int srow = tid >> 2;
    const int scol = (tid & 3) * 8;
    const uint32_t s_off = (uint32_t)(srow * 64 +
                           (((scol >> 3) ^ ((srow >> 1) & 3)) << 4));
    const int gm  = m0 + srow;
    const bool aok = (gm < M);
    const uint16_t* Arow = Ap + (size_t)gm * K + scol;
    const uint16_t* Wrow = Wp + (size_t)(n0 + srow) * K + scol;

    auto load_chunk = [&](int kb, int stg) {
        const uint32_t dst = smb + stg * STAGE_B + s_off;
#pragma unroll
        for (int s = 0; s < 3; s++) {
            cpa16(dst + s * TILE_B,       Arow + s * Aplane + kb, aok);
            cpa16(dst + (3 + s) * TILE_B, Wrow + s * Wplane + kb, true);
        }
    };

    // ---- ldmatrix lane mapping (both operands NON-trans) ----
    const int lr8   = lane & 7;
    const int rowA0 = wm + lr8 + ((lane >> 3) & 1) * 8;   // + mi*16
    const int rowB0 = wn + lr8 + (lane >> 4) * 8;         // + g*16
    const int akh   = lane >> 4;
    const int bkh   = (lane >> 3) & 1;
    const int aswz  = (rowA0 >> 1) & 3;   // invariant under +16
    const int bswz  = (rowB0 >> 1) & 3;

    float acc[2][4][4];
#pragma unroll
    for (int mi = 0; mi < 2; mi++)
#pragma unroll
        for (int ni = 0; ni < 4; ni++)
#pragma unroll
            for (int q = 0; q < 4; q++) acc[mi][ni][q] = 0.f;

    const int nc = K >> 5;

    // prime the pipeline: chunks 0 and 1
    load_chunk(0, 0);  CP_COMMIT();
    load_chunk(32, 1); CP_COMMIT();
    asm volatile("cp.async.wait_group 1;" ::: "memory");
    __syncthreads();

    int stage = 0;
    for (int c = 0; c < nc; c++) {
        if (c + 2 < nc) {
            int st2 = stage + 2; if (st2 >= 3) st2 -= 3;
            load_chunk((c + 2) << 5, st2);
            CP_COMMIT();
        }

        const uint32_t stgb = smb + stage * STAGE_B;

#pragma unroll
        for (int ks = 0; ks < 2; ks++) {
            const int kc = ks * 2;
            uint32_t af[3][2][4];
#pragma unroll
            for (int s = 0; s < 3; s++)
#pragma unroll
                for (int mi = 0; mi < 2; mi++)
                    ldsm4(af[s][mi],
                          stgb + s * TILE_B + (rowA0 + mi * 16) * 64 +
                          (((kc + akh) ^ aswz) << 4));
#pragma unroll
            for (int s = 0; s < 3; s++) {
                uint32_t bf[2][4];
#pragma unroll
                for (int g = 0; g < 2; g++)
                    ldsm4(bf[g],
                          stgb + (3 + s) * TILE_B + (rowB0 + g * 16) * 64 +
                          (((kc + bkh) ^ bswz) << 4));
#pragma unroll
                for (int as = 0; as <= 2 - s; as++)
#pragma unroll
                    for (int mi = 0; mi < 2; mi++)
#pragma unroll
                        for (int ni = 0; ni < 4; ni++)
                            mma16(acc[mi][ni], af[as][mi],
                                  &bf[ni >> 1][(ni & 1) * 2]);
            }
        }

        if (c + 2 < nc)
            asm volatile("cp.async.wait_group 1;" ::: "memory");
        else if (c + 1 < nc)
            asm volatile("cp.async.wait_group 0;" ::: "memory");
        __syncthreads();
        stage = (stage == 2) ? 0 : stage + 1;
    }

    // ---- epilogue: bias + activation; fp32 C and/or bf16x3 planes ----
#pragma unroll
    for (int mi = 0; mi < 2; mi++) {
        int row = m0 + wm + mi * 16 + (lane >> 2);
#pragma unroll
        for (int ni = 0; ni < 4; ni++) {
            int col = n0 + wn + (ni >> 1) * 16 + (ni & 1) * 8 + (lane & 3) * 2;
            float2 bv = *(const float2*)(bias + col);
            float v00 = acc[mi][ni][0] + bv.x, v01 = acc[mi][ni][1] + bv.y;
            float v10 = acc[mi][ni][2] + bv.x, v11 = acc[mi][ni][3] + bv.y;
            if (ACT) {
                v00 = fmaxf(v00, 0.f); v01 = fmaxf(v01, 0.f);
                v10 = fmaxf(v10, 0.f); v11 = fmaxf(v11, 0.f);
            }
#pragma unroll
            for (int half = 0; half < 2; half++) {
                int r = row + half * 8;
                if (r >= M) continue;
                float a = half ? v10 : v00;
                float b = half ? v11 : v01;
                size_t off = (size_t)r * N + col;
                if (EMITF) *(float2*)(C + off) = make_float2(a, b);
                if (EMITP) {
                    uint32_t h, m, l;
                    split2pack(a, b, h, m, l);
                    *(uint32_t*)(Cp + off)              = h;
                    *(uint32_t*)(Cp + Cplane + off)     = m;
                    *(uint32_t*)(Cp + 2 * Cplane + off) = l;
                }
            }
        }
    }
}

// ---------------- split: fp32 tensor -> 3 bf16 planes ----------------------
__global__ void split_kernel(const float* __restrict__ in,
                             uint16_t* __restrict__ p, long plane, int n)
{
    int i = (blockIdx.x * blockDim.x + threadIdx.x) * 4;
    if (i >= n) return;
    float4 v = *(const float4*)(in + i);
    uint32_t h0, m0, l0, h1, m1, l1;
    split2pack(v.x, v.y, h0, m0, l0);
    split2pack(v.z, v.w, h1, m1, l1);
    *(uint2*)(p + i)             = make_uint2(h0, h1);
    *(uint2*)(p + plane + i)     = make_uint2(m0, m1);
    *(uint2*)(p + 2 * plane + i) = make_uint2(l0, l1);
}

// ---------------- small helpers --------------------------------------------
__global__ void zero_kernel(float4* __restrict__ p, int n4)
{
    int i = blockIdx.x * blockDim.x + threadIdx.x;
    if (i < n4) p[i] = make_float4(0.f, 0.f, 0.f, 0.f);
}

__global__ void bcomb_kernel(const float* __restrict__ a,
                             const float* __restrict__ b,
                             float* __restrict__ c)
{
    int i = threadIdx.x;  // 1024 threads
    c[i] = a[i] + b[i];
}

// ---------------- scatter: agg[dst[e]] += H[rel[e]][src[e]] ----------------
__global__ void __launch_bounds__(256)
scatter_kernel(const float* __restrict__ H, const int* __restrict__ src,
               const int* __restrict__ dst, const int* __restrict__ rel,
               float* __restrict__ agg)
{
    int e = blockIdx.x * 8 + (threadIdx.x >> 5);
    if (e >= NE) return;
    int lane = threadIdx.x & 31;
    int s = src[e], d = dst[e], r = rel[e];
    const float4* hrow = (const float4*)(H + ((size_t)r * NN + s) * DD);
    float* arow = agg + (size_t)d * DD;
#pragma unroll
    for (int t = 0; t < 2; t++) {
        int idx = lane + t * 32;
        float4 v = __ldg(&hrow[idx]);
        asm volatile("red.global.add.v4.f32 [%0], {%1, %2, %3, %4};"
                     :: "l"(arow + idx * 4),
                        "f"(v.x), "f"(v.y), "f"(v.z), "f"(v.w)
                     : "memory");
    }
}

// ---------------- LSTM elementwise -> hn planes (c0 = h0 = 0) --------------
__global__ void lstm_kernel(const float* __restrict__ gates,
                            uint16_t* __restrict__ hp, long plane)
{
    int i = (blockIdx.x * blockDim.x + threadIdx.x) * 2;
    if (i >= NN * DD) return;
    int n = i >> 8;
    int c = i & 255;
    const float* gr = gates + (size_t)n * (4 * DD);
    float hv[2];
#pragma unroll
    for (int j = 0; j < 2; j++) {
        float ig = gr[c + j];
        float gg = gr[2 * DD + c + j];
        float og = gr[3 * DD + c + j];
        float si = 1.f / (1.f + expf(-ig));
        float cc = si * tanhf(gg);
        float so = 1.f / (1.f + expf(-og));
        hv[j] = so * tanhf(cc);
    }
    uint32_t h, m, l;
    split2pack(hv[0], hv[1], h, m, l);
    *(uint32_t*)(hp + i)             = h;
    *(uint32_t*)(hp + plane + i)     = m;
    *(uint32_t*)(hp + 2 * plane + i) = l;
}

// ---------------- launcher --------------------------------------------------
extern "C" void kernel_launch(void* const* d_in, const int* in_sizes, int n_in,
                              void* d_out, int out_size)
{
    const float* feat  = (const float*)d_in[0];
    const int*   src   = (const int*)d_in[1];
    const int*   dst   = (const int*)d_in[2];
    const int*   rel   = (const int*)d_in[3];
    const float* W_rel = (const float*)d_in[4];
    const float* b_rel = (const float*)d_in[5];
    const float* W_ih  = (const float*)d_in[6];
    const float* b_ih  = (const float*)d_in[7];
    const float* b_hh  = (const float*)d_in[8];
    const float* W1    = (const float*)d_in[9];
    const float* b1    = (const float*)d_in[10];
    const float* W2    = (const float*)d_in[11];
    const float* b2    = (const float*)d_in[12];
    const float* W3    = (const float*)d_in[13];
    const float* b3    = (const float*)d_in[14];
    float* out = (float*)d_out;

    float *H, *agg, *gates, *bc;
    uint16_t *featP, *TP, *aggP, *hnP, *x1P, *x2P;
    uint16_t *WrelP, *WihP, *W1P, *W2P, *W3P;
    cudaGetSymbolAddress((void**)&H,     g_H);
    cudaGetSymbolAddress((void**)&agg,   g_agg);
    cudaGetSymbolAddress((void**)&gates, g_gates);
    cudaGetSymbolAddress((void**)&bc,    g_bcomb);
    cudaGetSymbolAddress((void**)&featP, g_featP);
    cudaGetSymbolAddress((void**)&TP,    g_TP);
    cudaGetSymbolAddress((void**)&aggP,  g_aggP);
    cudaGetSymbolAddress((void**)&hnP,   g_hnP);
    cudaGetSymbolAddress((void**)&x1P,   g_x1P);
    cudaGetSymbolAddress((void**)&x2P,   g_x2P);
    cudaGetSymbolAddress((void**)&WrelP, g_WrelP);
    cudaGetSymbolAddress((void**)&WihP,  g_WihP);
    cudaGetSymbolAddress((void**)&W1P,   g_W1P);
    cudaGetSymbolAddress((void**)&W2P,   g_W2P);
    cudaGetSymbolAddress((void**)&W3P,   g_W3P);

    cudaFuncSetAttribute(tcgemm<1, 0, 0, 1>,
        cudaFuncAttributeMaxDynamicSharedMemorySize, GSMEM);
    cudaFuncSetAttribute(tcgemm<1, 0, 1, 0>,
        cudaFuncAttributeMaxDynamicSharedMemorySize, GSMEM);
    cudaFuncSetAttribute(tcgemm<0, 1, 1, 0>,
        cudaFuncAttributeMaxDynamicSharedMemorySize, GSMEM);
    cudaFuncSetAttribute(tcgemm<0, 0, 1, 0>,
        cudaFuncAttributeMaxDynamicSharedMemorySize, GSMEM);

    const int MB = (NN + 127) / 128;  // 79 row tiles
    const long ND  = (long)NN * DD;
    const long N128 = (long)NN * 128;

    // ---- prep: zero agg, combine bias, split static operands ----
    zero_kernel<<<(NN * DD / 4 + 255) / 256, 256>>>((float4*)agg, NN * DD / 4);
    bcomb_kernel<<<1, 1024>>>(b_ih, b_hh, bc);
    split_kernel<<<(NN * DD / 4 + 255) / 256, 256>>>(feat, featP, ND, NN * DD);
    split_kernel<<<(2 * DD * DD / 4 + 255) / 256, 256>>>(W_rel, WrelP,
                                                         2L * DD * DD, 2 * DD * DD);
    split_kernel<<<(4 * DD * DD / 4 + 255) / 256, 256>>>(W_ih, WihP,
                                                         4L * DD * DD, 4 * DD * DD);
    split_kernel<<<(128 * DD / 4 + 255) / 256, 256>>>(W1, W1P, 128L * DD, 128 * DD);
    split_kernel<<<(128 * 128 / 4 + 255) / 256, 256>>>(W2, W2P, 128L * 128, 128 * 128);
    split_kernel<<<(DD * 128 / 4 + 255) / 256, 256>>>(W3, W3P, (long)DD * 128, DD * 128);

    // ---- edge-NN deduped to per-(node, relation); relations via blockIdx.z
    // layer 1: feat planes -> T planes (fp32 T never materialized)
    tcgemm<1, 0, 0, 1><<<dim3(2, MB, 2), 512, GSMEM>>>(
        featP, ND, 0L,
        WrelP, 2L * DD * DD, (long)DD * DD,
        b_rel, (long)DD,
        nullptr, 0L,
        TP, 2L * ND, ND,
        NN, DD, DD);
    // layer 2: T planes -> H fp32 (scatter source)
    tcgemm<1, 0, 1, 0><<<dim3(2, MB, 2), 512, GSMEM>>>(
        TP, 2L * ND, ND,
        WrelP, 2L * DD * DD, (long)DD * DD,
        b_rel, (long)DD,
        H, ND,
        nullptr, 0L, 0L,
        NN, DD, DD);

    // ---- scatter-sum into destination nodes, then split agg ----
    scatter_kernel<<<NE / 8, 256>>>(H, src, dst, rel, agg);
    split_kernel<<<(NN * DD / 4 + 255) / 256, 256>>>(agg, aggP, ND, NN * DD);

    // ---- LSTM gates GEMM (i,g,o only; f-gate dead) + elementwise ----
    tcgemm<0, 1, 1, 0><<<dim3(6, MB, 1), 512, GSMEM>>>(
        aggP, ND, 0L,
        WihP, 4L * DD * DD, 0L,
        bc, 0L,
        gates, 0L,
        nullptr, 0L, 0L,
        NN, 4 * DD, DD);
    lstm_kernel<<<(NN * DD / 2 + 255) / 256, 256>>>(gates, hnP, ND);

    // ---- global-update MLP ----
    tcgemm<1, 0, 0, 1><<<dim3(1, MB, 1), 512, GSMEM>>>(
        hnP, ND, 0L,
        W1P, 128L * DD, 0L,
        b1, 0L,
        nullptr, 0L,
        x1P, N128, 0L,
        NN, 128, DD);
    tcgemm<1, 0, 0, 1><<<dim3(1, MB, 1), 512, GSMEM>>>(
        x1P, N128, 0L,
        W2P, 128L * 128, 0L,
        b2, 0L,
        nullptr, 0L,
        x2P, N128, 0L,
        NN, 128, 128);
    tcgemm<0, 0, 1, 0><<<dim3(2, MB, 1), 512, GSMEM>>>(
        x2P, N128, 0L,
        W3P, (long)DD * 128, 0L,
        b3, 0L,
        out, 0L,
        nullptr, 0L, 0L,
        NN, DD, 128);
}

// round 15
// speedup vs baseline: 1.5012x; 1.5012x over previous
#include <cuda_runtime.h>
#include <cuda_bf16.h>
#include <cstddef>
#include <cstdint>

#define NN 10000
#define NE 320000
#define DD 256

// ---------------- scratch (device globals; no runtime allocation) ----------
__device__ float g_T[2 * NN * DD];      // edge-NN layer-1 output, per relation
__device__ float g_H[2 * NN * DD];      // edge-NN layer-2 output, per relation
__device__ float g_agg[NN * DD];        // scatter-sum result
__device__ float g_gates[NN * 4 * DD];  // LSTM gates (f columns unwritten)
__device__ float g_hn[NN * DD];         // LSTM output
__device__ float g_x1[NN * 128];
__device__ float g_x2[NN * 128];
__device__ float g_bcomb[4 * DD];       // b_ih + b_hh

// ---------------- portable tensor-core helpers (NO a-suffix features) ------
__device__ __forceinline__ uint32_t smem_u32(const void* p)
{
    uint32_t a;
    asm("{ .reg .u64 t; cvta.to.shared.u64 t, %1; cvt.u32.u64 %0, t; }"
        : "=r"(a) : "l"(p));
    return a;
}

__device__ __forceinline__ void ldsm4(uint32_t* r, uint32_t addr)
{
    asm volatile("ldmatrix.sync.aligned.m8n8.x4.shared.b16 {%0,%1,%2,%3}, [%4];"
                 : "=r"(r[0]), "=r"(r[1]), "=r"(r[2]), "=r"(r[3]) : "r"(addr));
}

__device__ __forceinline__ void mma16(float* c, const uint32_t* a, const uint32_t* b)
{
    asm volatile(
        "mma.sync.aligned.m16n8k16.row.col.f32.bf16.bf16.f32 "
        "{%0,%1,%2,%3}, {%4,%5,%6,%7}, {%8,%9}, {%0,%1,%2,%3};"
        : "+f"(c[0]), "+f"(c[1]), "+f"(c[2]), "+f"(c[3])
        : "r"(a[0]), "r"(a[1]), "r"(a[2]), "r"(a[3]), "r"(b[0]), "r"(b[1]));
}

// ---------------- smem geometry ---------------------------------------------
// bf16 tile: 128 rows x 32 cols = 64 B/row = 8 KB. Per stage: A0 A1 W0 W1.
// Row layout: 4 chunks of 16B; swizzle chunk' = chunk ^ ((row>>1)&3) ->
// conflict-free for STS.128 stash and for 8-row ldmatrix fetches.
#define TILE_B  8192
#define STAGE_B (4 * TILE_B)
#define GSMEM   (2 * STAGE_B)           // 65536 B

// split 8 fp32 -> 2 x (8 bf16) by exact truncation; store 16B per level
__device__ __forceinline__ void pack2(const float4 v0, const float4 v1, char* p)
{
    const float vx[8] = {v0.x, v0.y, v0.z, v0.w, v1.x, v1.y, v1.z, v1.w};
    uint4 h, m;
    uint32_t* hp = (uint32_t*)&h;
    uint32_t* mp = (uint32_t*)&m;
#pragma unroll
    for (int j = 0; j < 4; j++) {
        float x0 = vx[2 * j], x1 = vx[2 * j + 1];
        uint32_t u0 = __float_as_uint(x0), u1 = __float_as_uint(x1);
        float r0 = x0 - __uint_as_float(u0 & 0xFFFF0000u);
        float r1 = x1 - __uint_as_float(u1 & 0xFFFF0000u);
        hp[j] = __byte_perm(u0, u1, 0x7632);
        mp[j] = __byte_perm(__float_as_uint(r0), __float_as_uint(r1), 0x7632);
    }
    *(uint4*)p            = h;
    *(uint4*)(p + TILE_B) = m;
}

// --------- bf16x3 tensor-core GEMM: C = act(A @ W^T + bias) -----------------
// 2-term exact split per operand; keep products hh + hm + mh (drop ~2^-16
// terms) -> ~16-17 effective mantissa bits, rel_err ~2-5e-5 over this net.
// A: [M,K] rm, W: [N,K] rm, bias: [N], C: [M,N] rm.
// 128x128 block, BK=32, 512 threads = 16 warps (4m x 4n), warp 32x32.
// Double-buffered smem. blockIdx.z batches via strides. N%128==0, K%32==0.
// SKIPF: remap column tiles >=2 -> +256 (skip dead LSTM f-gate columns).
template <int ACT, int SKIPF>
__global__ void __launch_bounds__(512)
tcgemm(const float* __restrict__ A, const float* __restrict__ W,
       const float* __restrict__ bias, float* __restrict__ C,
       int M, int N, int K,
       long sA, long sW, long sB, long sC)
{
    A    += (long)blockIdx.z * sA;
    W    += (long)blockIdx.z * sW;
    bias += (long)blockIdx.z * sB;
    C    += (long)blockIdx.z * sC;

    extern __shared__ char smc[];
    const uint32_t smb = smem_u32(smc);

    const int tid  = threadIdx.x;
    const int lane = tid & 31;
    const int wid  = tid >> 5;
    const int wm   = (wid & 3) * 32;
    const int wn   = (wid >> 2) * 32;

    const int m0 = blockIdx.y * 128;
    int n0 = blockIdx.x * 128;
    if (SKIPF && blockIdx.x >= 2) n0 += 256;

    // ---- stash mapping: thread -> (row 0..127, col group of 8) ----
    const int srow = tid >> 2;
    const int scol = (tid & 3) * 8;
    const uint32_t s_off = (uint32_t)(srow * 64 +
                           (((scol >> 3) ^ ((srow >> 1) & 3)) << 4));
    const int gm = m0 + srow;
    const float* Arow = A + (size_t)gm * K;
    const float* Wrow = W + (size_t)(n0 + srow) * K;
    const float4 fz = make_float4(0.f, 0.f, 0.f, 0.f);

    // ---- ldmatrix lane mapping (both operands NON-trans) ----
    const int lr8   = lane & 7;
    const int rowA0 = wm + lr8 + ((lane >> 3) & 1) * 8;   // + mi*16
    const int rowB0 = wn + lr8 + (lane >> 4) * 8;         // + g*16
    const int akh   = lane >> 4;          // A k-half select
    const int bkh   = (lane >> 3) & 1;    // B k-half select
    const int aswz  = (rowA0 >> 1) & 3;   // invariant under +16
    const int bswz  = (rowB0 >> 1) & 3;

    float acc[2][4][4];
#pragma unroll
    for (int mi = 0; mi < 2; mi++)
#pragma unroll
        for (int ni = 0; ni < 4; ni++)
#pragma unroll
            for (int q = 0; q < 4; q++) acc[mi][ni][q] = 0.f;

    // ---- chunk-0 global loads ----
    float4 pa0, pa1, pw0, pw1;
    pa0 = (gm < M) ? *(const float4*)(Arow + scol)     : fz;
    pa1 = (gm < M) ? *(const float4*)(Arow + scol + 4) : fz;
    pw0 = *(const float4*)(Wrow + scol);
    pw1 = *(const float4*)(Wrow + scol + 4);

    auto stash = [&](int stg) {
        char* base = smc + stg * STAGE_B;
        pack2(pa0, pa1, base + s_off);
        pack2(pw0, pw1, base + 2 * TILE_B + s_off);
    };

    stash(0);
    __syncthreads();

    const int nc = K >> 5;
    int stage = 0;

    for (int c = 0; c < nc; c++) {
        // prefetch chunk c+1 (overlaps with MMA work below)
        if (c + 1 < nc) {
            int kb = (c + 1) << 5;
            pa0 = (gm < M) ? *(const float4*)(Arow + kb + scol)     : fz;
            pa1 = (gm < M) ? *(const float4*)(Arow + kb + scol + 4) : fz;
            pw0 = *(const float4*)(Wrow + kb + scol);
            pw1 = *(const float4*)(Wrow + kb + scol + 4);
        }

        const uint32_t stgb = smb + stage * STAGE_B;

#pragma unroll
        for (int ks = 0; ks < 2; ks++) {
            const int kc = ks * 2;
            uint32_t af[2][2][4];
#pragma unroll
            for (int s = 0; s < 2; s++)
#pragma unroll
                for (int mi = 0; mi < 2; mi++)
                    ldsm4(af[s][mi],
                          stgb + s * TILE_B + (rowA0 + mi * 16) * 64 +
                          (((kc + akh) ^ aswz) << 4));
#pragma unroll
            for (int s = 0; s < 2; s++) {
                uint32_t bf[2][4];
#pragma unroll
                for (int g = 0; g < 2; g++)
                    ldsm4(bf[g],
                          stgb + (2 + s) * TILE_B + (rowB0 + g * 16) * 64 +
                          (((kc + bkh) ^ bswz) << 4));
                // products with A-level 'as' such that as + s <= 1:
                // (hh), (hm), (mh) — drop second-order mm
#pragma unroll
                for (int as = 0; as <= 1 - s; as++)
#pragma unroll
                    for (int mi = 0; mi < 2; mi++)
#pragma unroll
                        for (int ni = 0; ni < 4; ni++)
                            mma16(acc[mi][ni], af[as][mi],
                                  &bf[ni >> 1][(ni & 1) * 2]);
            }
        }

        if (c + 1 < nc) stash(stage ^ 1);
        __syncthreads();
        stage ^= 1;
    }

    // ---- epilogue: bias + activation, float2 stores ----
#pragma unroll
    for (int mi = 0; mi < 2; mi++) {
        int row = m0 + wm + mi * 16 + (lane >> 2);
#pragma unroll
        for (int ni = 0; ni < 4; ni++) {
            int col = n0 + wn + (ni >> 1) * 16 + (ni & 1) * 8 + (lane & 3) * 2;
            float2 bv = *(const float2*)(bias + col);
            float2 o0, o1;
            o0.x = acc[mi][ni][0] + bv.x;
            o0.y = acc[mi][ni][1] + bv.y;
            o1.x = acc[mi][ni][2] + bv.x;
            o1.y = acc[mi][ni][3] + bv.y;
            if (ACT) {
                o0.x = fmaxf(o0.x, 0.f); o0.y = fmaxf(o0.y, 0.f);
                o1.x = fmaxf(o1.x, 0.f); o1.y = fmaxf(o1.y, 0.f);
            }
            if (row < M)     *(float2*)(C + (size_t)row * N + col)       = o0;
            if (row + 8 < M) *(float2*)(C + (size_t)(row + 8) * N + col) = o1;
        }
    }
}

// ---------------- small helpers --------------------------------------------
__global__ void zero_kernel(float4* __restrict__ p, int n4)
{
    int i = blockIdx.x * blockDim.x + threadIdx.x;
    if (i < n4) p[i] = make_float4(0.f, 0.f, 0.f, 0.f);
}

__global__ void bcomb_kernel(const float* __restrict__ a,
                             const float* __restrict__ b,
                             float* __restrict__ c)
{
    int i = threadIdx.x;  // 1024 threads
    c[i] = a[i] + b[i];
}

// ---------------- scatter: agg[dst[e]] += H[rel[e]][src[e]] ----------------
__global__ void __launch_bounds__(256)
scatter_kernel(const float* __restrict__ H, const int* __restrict__ src,
               const int* __restrict__ dst, const int* __restrict__ rel,
               float* __restrict__ agg)
{
    int e = blockIdx.x * 8 + (threadIdx.x >> 5);
    if (e >= NE) return;
    int lane = threadIdx.x & 31;
    int s = src[e], d = dst[e], r = rel[e];
    const float4* hrow = (const float4*)(H + ((size_t)r * NN + s) * DD);
    float* arow = agg + (size_t)d * DD;
#pragma unroll
    for (int t = 0; t < 2; t++) {
        int idx = lane + t * 32;
        float4 v = __ldg(&hrow[idx]);
        asm volatile("red.global.add.v4.f32 [%0], {%1, %2, %3, %4};"
                     :: "l"(arow + idx * 4),
                        "f"(v.x), "f"(v.y), "f"(v.z), "f"(v.w)
                     : "memory");
    }
}

// ---------------- LSTM elementwise (c0 = h0 = 0, f-gate dead) --------------
__global__ void lstm_kernel(const float* __restrict__ gates,
                            float* __restrict__ hn)
{
    int i = blockIdx.x * blockDim.x + threadIdx.x;
    if (i >= NN * DD) return;
    int n = i >> 8;
    int c = i & 255;
    const float* gr = gates + (size_t)n * (4 * DD);
    float ig = gr[c];
    float gg = gr[2 * DD + c];
    float og = gr[3 * DD + c];
    float si = 1.f / (1.f + expf(-ig));
    float cc = si * tanhf(gg);
    float so = 1.f / (1.f + expf(-og));
    hn[i] = so * tanhf(cc);
}

// ---------------- launcher --------------------------------------------------
extern "C" void kernel_launch(void* const* d_in, const int* in_sizes, int n_in,
                              void* d_out, int out_size)
{
    const float* feat  = (const float*)d_in[0];
    const int*   src   = (const int*)d_in[1];
    const int*   dst   = (const int*)d_in[2];
    const int*   rel   = (const int*)d_in[3];
    const float* W_rel = (const float*)d_in[4];
    const float* b_rel = (const float*)d_in[5];
    const float* W_ih  = (const float*)d_in[6];
    const float* b_ih  = (const float*)d_in[7];
    const float* b_hh  = (const float*)d_in[8];
    const float* W1    = (const float*)d_in[9];
    const float* b1    = (const float*)d_in[10];
    const float* W2    = (const float*)d_in[11];
    const float* b2    = (const float*)d_in[12];
    const float* W3    = (const float*)d_in[13];
    const float* b3    = (const float*)d_in[14];
    float* out = (float*)d_out;

    float *T, *H, *agg, *gates, *hn, *x1, *x2, *bc;
    cudaGetSymbolAddress((void**)&T,     g_T);
    cudaGetSymbolAddress((void**)&H,     g_H);
    cudaGetSymbolAddress((void**)&agg,   g_agg);
    cudaGetSymbolAddress((void**)&gates, g_gates);
    cudaGetSymbolAddress((void**)&hn,    g_hn);
    cudaGetSymbolAddress((void**)&x1,    g_x1);
    cudaGetSymbolAddress((void**)&x2,    g_x2);
    cudaGetSymbolAddress((void**)&bc,    g_bcomb);

    // allow 64KB dynamic smem (host-side state; no stream work enqueued)
    cudaFuncSetAttribute(tcgemm<1, 0>,
        cudaFuncAttributeMaxDynamicSharedMemorySize, GSMEM);
    cudaFuncSetAttribute(tcgemm<0, 1>,
        cudaFuncAttributeMaxDynamicSharedMemorySize, GSMEM);
    cudaFuncSetAttribute(tcgemm<0, 0>,
        cudaFuncAttributeMaxDynamicSharedMemorySize, GSMEM);

    const int MB = (NN + 127) / 128;  // 79 row tiles
    const long ND = (long)NN * DD;

    // independent prep work first
    zero_kernel<<<(NN * DD / 4 + 255) / 256, 256>>>((float4*)agg, NN * DD / 4);
    bcomb_kernel<<<1, 1024>>>(b_ih, b_hh, bc);

    // edge-NN deduped to per-(node, relation), both relations via blockIdx.z
    tcgemm<1, 0><<<dim3(2, MB, 2), 512, GSMEM>>>(
        feat, W_rel, b_rel, T, NN, DD, DD,
        0L, (long)DD * DD, (long)DD, ND);
    tcgemm<1, 0><<<dim3(2, MB, 2), 512, GSMEM>>>(
        T, W_rel, b_rel, H, NN, DD, DD,
        ND, (long)DD * DD, (long)DD, ND);

    // scatter-sum into destination nodes
    scatter_kernel<<<NE / 8, 256>>>(H, src, dst, rel, agg);

    // LSTM gates GEMM: only i,g,o gate columns (f-gate dead, grid.x=6 remapped)
    tcgemm<0, 1><<<dim3(6, MB, 1), 512, GSMEM>>>(
        agg, W_ih, bc, gates, NN, 4 * DD, DD, 0L, 0L, 0L, 0L);
    lstm_kernel<<<(NN * DD + 255) / 256, 256>>>(gates, hn);

    // global-update MLP
    tcgemm<1, 0><<<dim3(1, MB, 1), 512, GSMEM>>>(hn, W1, b1, x1, NN, 128, DD,
                                                 0L, 0L, 0L, 0L);
    tcgemm<1, 0><<<dim3(1, MB, 1), 512, GSMEM>>>(x1, W2, b2, x2, NN, 128, 128,
                                                 0L, 0L, 0L, 0L);
    tcgemm<0, 0><<<dim3(2, MB, 1), 512, GSMEM>>>(x2, W3, b3, out, NN, DD, 128,
                                                 0L, 0L, 0L, 0L);
}

// round 16
// speedup vs baseline: 1.5155x; 1.0095x over previous
#include <cuda_runtime.h>
#include <cuda_bf16.h>
#include <cstddef>
#include <cstdint>

#define NN 10000
#define NE 320000
#define DD 256

// ---------------- scratch (device globals; no runtime allocation) ----------
__device__ float g_T[2 * NN * DD];      // edge-NN layer-1 output, per relation
__device__ float g_H[2 * NN * DD];      // edge-NN layer-2 output, per relation
__device__ float g_agg[NN * DD];        // scatter-sum result
__device__ float g_gates[NN * 4 * DD];  // LSTM gates (f columns unwritten)
__device__ float g_hn[NN * DD];         // LSTM output
__device__ float g_x1[NN * 128];
__device__ float g_x2[NN * 128];
__device__ float g_bcomb[4 * DD];       // b_ih + b_hh

// ---------------- portable tensor-core helpers (NO a-suffix features) ------
__device__ __forceinline__ uint32_t smem_u32(const void* p)
{
    uint32_t a;
    asm("{ .reg .u64 t; cvta.to.shared.u64 t, %1; cvt.u32.u64 %0, t; }"
        : "=r"(a) : "l"(p));
    return a;
}

__device__ __forceinline__ void ldsm4(uint32_t* r, uint32_t addr)
{
    asm volatile("ldmatrix.sync.aligned.m8n8.x4.shared.b16 {%0,%1,%2,%3}, [%4];"
                 : "=r"(r[0]), "=r"(r[1]), "=r"(r[2]), "=r"(r[3]) : "r"(addr));
}

__device__ __forceinline__ void mma16(float* c, const uint32_t* a, const uint32_t* b)
{
    asm volatile(
        "mma.sync.aligned.m16n8k16.row.col.f32.bf16.bf16.f32 "
        "{%0,%1,%2,%3}, {%4,%5,%6,%7}, {%8,%9}, {%0,%1,%2,%3};"
        : "+f"(c[0]), "+f"(c[1]), "+f"(c[2]), "+f"(c[3])
        : "r"(a[0]), "r"(a[1]), "r"(a[2]), "r"(a[3]), "r"(b[0]), "r"(b[1]));
}

// ---------------- smem geometry ---------------------------------------------
// A tile: 64 rows x 32 cols bf16 = 4 KB/plane; W tile: 128 rows x 32 = 8 KB.
// Per stage: A_h A_m W_h W_m = 24 KB; 2 stages = 48 KB -> 2 CTAs/SM.
// Row layout: 16B chunks; swizzle chunk' = chunk ^ ((row>>1)&3) ->
// conflict-free for STS.128 stash and 8-row ldmatrix fetches.
#define TILE_A  4096
#define TILE_W  8192
#define WOFF    (2 * TILE_A)
#define STAGE_B (2 * TILE_A + 2 * TILE_W)   // 24576
#define GSMEM   (2 * STAGE_B)               // 49152

// split 8 fp32 -> 2 x (8 bf16) by exact truncation; store 16B per level.
// 'stride' = plane stride in bytes (TILE_A or TILE_W).
__device__ __forceinline__ void pack2(const float4 v0, const float4 v1,
                                      char* p, int stride)
{
    const float vx[8] = {v0.x, v0.y, v0.z, v0.w, v1.x, v1.y, v1.z, v1.w};
    uint4 h, m;
    uint32_t* hp = (uint32_t*)&h;
    uint32_t* mp = (uint32_t*)&m;
#pragma unroll
    for (int j = 0; j < 4; j++) {
        float x0 = vx[2 * j], x1 = vx[2 * j + 1];
        uint32_t u0 = __float_as_uint(x0), u1 = __float_as_uint(x1);
        float r0 = x0 - __uint_as_float(u0 & 0xFFFF0000u);
        float r1 = x1 - __uint_as_float(u1 & 0xFFFF0000u);
        hp[j] = __byte_perm(u0, u1, 0x7632);
        mp[j] = __byte_perm(__float_as_uint(r0), __float_as_uint(r1), 0x7632);
    }
    *(uint4*)p            = h;
    *(uint4*)(p + stride) = m;
}

// --------- bf16x3 tensor-core GEMM: C = act(A @ W^T + bias) -----------------
// 2-term exact split per operand; keep products hh + hm + mh.
// A: [M,K] rm, W: [N,K] rm, bias: [N], C: [M,N] rm.
// 64x128 block tile, BK=32, 256 threads = 8 warps (2m x 4n), warp 32x32.
// 2 CTAs/SM (indep. barriers hide stash/sync latency). N%128==0, K%32==0.
// SKIPF: remap column tiles >=2 -> +256 (skip dead LSTM f-gate columns).
template <int ACT, int SKIPF>
__global__ void __launch_bounds__(256, 2)
tcgemm(const float* __restrict__ A, const float* __restrict__ W,
       const float* __restrict__ bias, float* __restrict__ C,
       int M, int N, int K,
       long sA, long sW, long sB, long sC)
{
    A    += (long)blockIdx.z * sA;
    W    += (long)blockIdx.z * sW;
    bias += (long)blockIdx.z * sB;
    C    += (long)blockIdx.z * sC;

    extern __shared__ char smc[];
    const uint32_t smb = smem_u32(smc);

    const int tid  = threadIdx.x;
    const int lane = tid & 31;
    const int wid  = tid >> 5;
    const int wm   = (wid & 1) * 32;     // 2 m-warps
    const int wn   = (wid >> 1) * 32;    // 4 n-warps

    const int m0 = blockIdx.y * 64;
    int n0 = blockIdx.x * 128;
    if (SKIPF && blockIdx.x >= 2) n0 += 256;

    // ---- A stash mapping: thread -> (row 0..63, 8-col group) ----
    const int srow = tid >> 2;
    const int scol = (tid & 3) * 8;
    const uint32_t a_off = (uint32_t)(srow * 64 +
                           (((scol >> 3) ^ ((srow >> 1) & 3)) << 4));
    const int gm = m0 + srow;
    const float* Arow = A + (size_t)gm * K;

    // ---- W stash mapping: thread -> (row 0..127, 16-col group) ----
    const int wrow  = tid >> 1;          // 0..127
    const int wcolg = (tid & 1) * 2;     // chunk pair {0,1} or {2,3}
    const int wswz  = (wrow >> 1) & 3;
    const uint32_t w_off0 = (uint32_t)(wrow * 64 + ((wcolg ^ wswz) << 4));
    const uint32_t w_off1 = (uint32_t)(wrow * 64 + (((wcolg + 1) ^ wswz) << 4));
    const float* Wrow = W + (size_t)(n0 + wrow) * K + wcolg * 8;

    const float4 fz = make_float4(0.f, 0.f, 0.f, 0.f);

    // ---- ldmatrix lane mapping (both operands NON-trans) ----
    const int lr8   = lane & 7;
    const int rowA0 = wm + lr8 + ((lane >> 3) & 1) * 8;   // + mi*16, <64
    const int rowB0 = wn + lr8 + (lane >> 4) * 8;         // + g*16
    const int akh   = lane >> 4;          // A k-half select
    const int bkh   = (lane >> 3) & 1;    // B k-half select
    const int aswz  = (rowA0 >> 1) & 3;   // invariant under +16
    const int bswz  = (rowB0 >> 1) & 3;

    float acc[2][4][4];
#pragma unroll
    for (int mi = 0; mi < 2; mi++)
#pragma unroll
        for (int ni = 0; ni < 4; ni++)
#pragma unroll
            for (int q = 0; q < 4; q++) acc[mi][ni][q] = 0.f;

    // ---- chunk-0 global loads ----
    float4 pa0, pa1, pw0, pw1, pw2, pw3;
    pa0 = (gm < M) ? *(const float4*)(Arow + scol)     : fz;
    pa1 = (gm < M) ? *(const float4*)(Arow + scol + 4) : fz;
    pw0 = *(const float4*)(Wrow + 0);
    pw1 = *(const float4*)(Wrow + 4);
    pw2 = *(const float4*)(Wrow + 8);
    pw3 = *(const float4*)(Wrow + 12);

    auto stash = [&](int stg) {
        char* base = smc + stg * STAGE_B;
        pack2(pa0, pa1, base + a_off, TILE_A);
        pack2(pw0, pw1, base + WOFF + w_off0, TILE_W);
        pack2(pw2, pw3, base + WOFF + w_off1, TILE_W);
    };

    stash(0);
    __syncthreads();

    const int nc = K >> 5;
    int stage = 0;

    for (int c = 0; c < nc; c++) {
        // prefetch chunk c+1 (overlaps with MMA work below)
        if (c + 1 < nc) {
            int kb = (c + 1) << 5;
            pa0 = (gm < M) ? *(const float4*)(Arow + kb + scol)     : fz;
            pa1 = (gm < M) ? *(const float4*)(Arow + kb + scol + 4) : fz;
            pw0 = *(const float4*)(Wrow + kb + 0);
            pw1 = *(const float4*)(Wrow + kb + 4);
            pw2 = *(const float4*)(Wrow + kb + 8);
            pw3 = *(const float4*)(Wrow + kb + 12);
        }

        const uint32_t stgb = smb + stage * STAGE_B;

#pragma unroll
        for (int ks = 0; ks < 2; ks++) {
            const int kc = ks * 2;
            uint32_t af[2][2][4];
#pragma unroll
            for (int s = 0; s < 2; s++)
#pragma unroll
                for (int mi = 0; mi < 2; mi++)
                    ldsm4(af[s][mi],
                          stgb + s * TILE_A + (rowA0 + mi * 16) * 64 +
                          (((kc + akh) ^ aswz) << 4));
#pragma unroll
            for (int s = 0; s < 2; s++) {
                uint32_t bf[2][4];
#pragma unroll
                for (int g = 0; g < 2; g++)
                    ldsm4(bf[g],
                          stgb + WOFF + s * TILE_W + (rowB0 + g * 16) * 64 +
                          (((kc + bkh) ^ bswz) << 4));
                // products hh, hm, mh (as + s <= 1); drop second-order mm
#pragma unroll
                for (int as = 0; as <= 1 - s; as++)
#pragma unroll
                    for (int mi = 0; mi < 2; mi++)
#pragma unroll
                        for (int ni = 0; ni < 4; ni++)
                            mma16(acc[mi][ni], af[as][mi],
                                  &bf[ni >> 1][(ni & 1) * 2]);
            }
        }

        if (c + 1 < nc) stash(stage ^ 1);
        __syncthreads();
        stage ^= 1;
    }

    // ---- epilogue: bias + activation, float2 stores ----
#pragma unroll
    for (int mi = 0; mi < 2; mi++) {
        int row = m0 + wm + mi * 16 + (lane >> 2);
#pragma unroll
        for (int ni = 0; ni < 4; ni++) {
            int col = n0 + wn + (ni >> 1) * 16 + (ni & 1) * 8 + (lane & 3) * 2;
            float2 bv = *(const float2*)(bias + col);
            float2 o0, o1;
            o0.x = acc[mi][ni][0] + bv.x;
            o0.y = acc[mi][ni][1] + bv.y;
            o1.x = acc[mi][ni][2] + bv.x;
            o1.y = acc[mi][ni][3] + bv.y;
            if (ACT) {
                o0.x = fmaxf(o0.x, 0.f); o0.y = fmaxf(o0.y, 0.f);
                o1.x = fmaxf(o1.x, 0.f); o1.y = fmaxf(o1.y, 0.f);
            }
            if (row < M)     *(float2*)(C + (size_t)row * N + col)       = o0;
            if (row + 8 < M) *(float2*)(C + (size_t)(row + 8) * N + col) = o1;
        }
    }
}

// ---------------- small helpers --------------------------------------------
__global__ void zero_kernel(float4* __restrict__ p, int n4)
{
    int i = blockIdx.x * blockDim.x + threadIdx.x;
    if (i < n4) p[i] = make_float4(0.f, 0.f, 0.f, 0.f);
}

__global__ void bcomb_kernel(const float* __restrict__ a,
                             const float* __restrict__ b,
                             float* __restrict__ c)
{
    int i = threadIdx.x;  // 1024 threads
    c[i] = a[i] + b[i];
}

// ---------------- scatter: agg[dst[e]] += H[rel[e]][src[e]] ----------------
__global__ void __launch_bounds__(256)
scatter_kernel(const float* __restrict__ H, const int* __restrict__ src,
               const int* __restrict__ dst, const int* __restrict__ rel,
               float* __restrict__ agg)
{
    int e = blockIdx.x * 8 + (threadIdx.x >> 5);
    if (e >= NE) return;
    int lane = threadIdx.x & 31;
    int s = src[e], d = dst[e], r = rel[e];
    const float4* hrow = (const float4*)(H + ((size_t)r * NN + s) * DD);
    float* arow = agg + (size_t)d * DD;
#pragma unroll
    for (int t = 0; t < 2; t++) {
        int idx = lane + t * 32;
        float4 v = __ldg(&hrow[idx]);
        asm volatile("red.global.add.v4.f32 [%0], {%1, %2, %3, %4};"
                     :: "l"(arow + idx * 4),
                        "f"(v.x), "f"(v.y), "f"(v.z), "f"(v.w)
                     : "memory");
    }
}

// ---------------- LSTM elementwise (c0 = h0 = 0, f-gate dead) --------------
__global__ void lstm_kernel(const float* __restrict__ gates,
                            float* __restrict__ hn)
{
    int i = blockIdx.x * blockDim.x + threadIdx.x;
    if (i >= NN * DD) return;
    int n = i >> 8;
    int c = i & 255;
    const float* gr = gates + (size_t)n * (4 * DD);
    float ig = gr[c];
    float gg = gr[2 * DD + c];
    float og = gr[3 * DD + c];
    float si = 1.f / (1.f + expf(-ig));
    float cc = si * tanhf(gg);
    float so = 1.f / (1.f + expf(-og));
    hn[i] = so * tanhf(cc);
}

// ---------------- launcher --------------------------------------------------
extern "C" void kernel_launch(void* const* d_in, const int* in_sizes, int n_in,
                              void* d_out, int out_size)
{
    const float* feat  = (const float*)d_in[0];
    const int*   src   = (const int*)d_in[1];
    const int*   dst   = (const int*)d_in[2];
    const int*   rel   = (const int*)d_in[3];
    const float* W_rel = (const float*)d_in[4];
    const float* b_rel = (const float*)d_in[5];
    const float* W_ih  = (const float*)d_in[6];
    const float* b_ih  = (const float*)d_in[7];
    const float* b_hh  = (const float*)d_in[8];
    const float* W1    = (const float*)d_in[9];
    const float* b1    = (const float*)d_in[10];
    const float* W2    = (const float*)d_in[11];
    const float* b2    = (const float*)d_in[12];
    const float* W3    = (const float*)d_in[13];
    const float* b3    = (const float*)d_in[14];
    float* out = (float*)d_out;

    float *T, *H, *agg, *gates, *hn, *x1, *x2, *bc;
    cudaGetSymbolAddress((void**)&T,     g_T);
    cudaGetSymbolAddress((void**)&H,     g_H);
    cudaGetSymbolAddress((void**)&agg,   g_agg);
    cudaGetSymbolAddress((void**)&gates, g_gates);
    cudaGetSymbolAddress((void**)&hn,    g_hn);
    cudaGetSymbolAddress((void**)&x1,    g_x1);
    cudaGetSymbolAddress((void**)&x2,    g_x2);
    cudaGetSymbolAddress((void**)&bc,    g_bcomb);

    cudaFuncSetAttribute(tcgemm<1, 0>,
        cudaFuncAttributeMaxDynamicSharedMemorySize, GSMEM);
    cudaFuncSetAttribute(tcgemm<0, 1>,
        cudaFuncAttributeMaxDynamicSharedMemorySize, GSMEM);
    cudaFuncSetAttribute(tcgemm<0, 0>,
        cudaFuncAttributeMaxDynamicSharedMemorySize, GSMEM);

    const int MB = (NN + 63) / 64;    // 157 row tiles
    const long ND = (long)NN * DD;

    // independent prep work first
    zero_kernel<<<(NN * DD / 4 + 255) / 256, 256>>>((float4*)agg, NN * DD / 4);
    bcomb_kernel<<<1, 1024>>>(b_ih, b_hh, bc);

    // edge-NN deduped to per-(node, relation), both relations via blockIdx.z
    tcgemm<1, 0><<<dim3(2, MB, 2), 256, GSMEM>>>(
        feat, W_rel, b_rel, T, NN, DD, DD,
        0L, (long)DD * DD, (long)DD, ND);
    tcgemm<1, 0><<<dim3(2, MB, 2), 256, GSMEM>>>(
        T, W_rel, b_rel, H, NN, DD, DD,
        ND, (long)DD * DD, (long)DD, ND);

    // scatter-sum into destination nodes
    scatter_kernel<<<NE / 8, 256>>>(H, src, dst, rel, agg);

    // LSTM gates GEMM: only i,g,o gate columns (f-gate dead, grid.x=6 remapped)
    tcgemm<0, 1><<<dim3(6, MB, 1), 256, GSMEM>>>(
        agg, W_ih, bc, gates, NN, 4 * DD, DD, 0L, 0L, 0L, 0L);
    lstm_kernel<<<(NN * DD + 255) / 256, 256>>>(gates, hn);

    // global-update MLP
    tcgemm<1, 0><<<dim3(1, MB, 1), 256, GSMEM>>>(hn, W1, b1, x1, NN, 128, DD,
                                                 0L, 0L, 0L, 0L);
    tcgemm<1, 0><<<dim3(1, MB, 1), 256, GSMEM>>>(x1, W2, b2, x2, NN, 128, 128,
                                                 0L, 0L, 0L, 0L);
    tcgemm<0, 0><<<dim3(2, MB, 1), 256, GSMEM>>>(x2, W3, b3, out, NN, DD, 128,
                                                 0L, 0L, 0L, 0L);
}